// round 15
// baseline (speedup 1.0000x reference)
#include <cuda_runtime.h>
#include <cuda_fp16.h>
#include <math.h>
#include <stdint.h>

#define HID 768
#define HEADS 12
#define DH 64
#define WW 256
#define NC 16
#define FFNDIM 3072
#define NLAB 8921
#define BB 2
#define SS 4096
#define NTOK (BB*SS)

// -------- scratch (device globals; no allocation allowed) --------
__device__ __align__(256) float g_x[NTOK*HID];
__device__ __align__(256) float g_q[NTOK*HID];
__device__ __align__(256) float g_k[NTOK*HID];
__device__ __align__(256) float g_v[NTOK*HID];
__device__ __align__(256) float g_kg[NTOK*HID];
__device__ __align__(256) float g_vg[NTOK*HID];
__device__ __align__(256) float g_tmp[NTOK*HID];
__device__ __align__(256) float g_qg0[BB*HID];
__device__ __align__(256) float g_gm[BB*HEADS*16];
__device__ __align__(256) float g_gl[BB*HEADS*16];
__device__ __align__(256) float g_go[BB*HEADS*16*DH];
__device__ __align__(256) __half g_wt[(size_t)2*6*HID*HID];
__device__ __align__(256) __half g_w1t[(size_t)2*FFNDIM*HID];
__device__ __align__(256) __half g_w2t[(size_t)2*HID*FFNDIM];
__device__ __align__(256) __half g_ab[(size_t)NTOK*FFNDIM];   // FFN intermediate fp16
__device__ __align__(256) __half g_ab2[(size_t)NTOK*HID];     // HID-wide fp16 activations

// ==================== small helpers ====================
__device__ __forceinline__ uint32_t s2u(const void* p) {
    uint32_t a;
    asm("{ .reg .u64 t; cvta.to.shared.u64 t, %1; cvt.u32.u64 %0, t; }" : "=r"(a) : "l"(p));
    return a;
}
__device__ __forceinline__ void cp16(uint32_t s, const void* g) {
    asm volatile("cp.async.cg.shared.global [%0], [%1], 16;" :: "r"(s), "l"(g));
}
__device__ __forceinline__ void ldsm4(uint32_t* r, uint32_t addr) {
    asm volatile("ldmatrix.sync.aligned.m8n8.x4.shared.b16 {%0,%1,%2,%3}, [%4];"
        : "=r"(r[0]), "=r"(r[1]), "=r"(r[2]), "=r"(r[3]) : "r"(addr));
}
__device__ __forceinline__ void mma_f16(float* d, const uint32_t* a, uint32_t b0, uint32_t b1) {
    asm volatile(
        "mma.sync.aligned.m16n8k16.row.col.f32.f16.f16.f32 "
        "{%0,%1,%2,%3}, {%4,%5,%6,%7}, {%8,%9}, {%0,%1,%2,%3};"
        : "+f"(d[0]), "+f"(d[1]), "+f"(d[2]), "+f"(d[3])
        : "r"(a[0]), "r"(a[1]), "r"(a[2]), "r"(a[3]), "r"(b0), "r"(b1));
}
// ---- packed fp32x2 (exact per-lane fp32 ops) ----
__device__ __forceinline__ void fma2(unsigned long long& d, unsigned long long a, unsigned long long b) {
    asm("fma.rn.f32x2 %0, %1, %2, %0;" : "+l"(d) : "l"(a), "l"(b));
}
__device__ __forceinline__ unsigned long long mul2(unsigned long long a, unsigned long long b) {
    unsigned long long r;
    asm("mul.rn.f32x2 %0, %1, %2;" : "=l"(r) : "l"(a), "l"(b));
    return r;
}
__device__ __forceinline__ unsigned long long pk2(float lo, float hi) {
    unsigned long long r;
    asm("mov.b64 %0, {%1, %2};" : "=l"(r) : "f"(lo), "f"(hi));
    return r;
}
__device__ __forceinline__ float2 upk2(unsigned long long v) {
    float2 f;
    asm("mov.b64 {%0, %1}, %2;" : "=f"(f.x), "=f"(f.y) : "l"(v));
    return f;
}

// -------- block reduction helpers (256 threads) --------
__device__ __forceinline__ float blk_sum256(float v, float* red) {
    #pragma unroll
    for (int o = 16; o > 0; o >>= 1) v += __shfl_xor_sync(0xffffffffu, v, o);
    int w = threadIdx.x >> 5, ln = threadIdx.x & 31;
    if (ln == 0) red[w] = v;
    __syncthreads();
    if (w == 0) {
        float t = (ln < 8) ? red[ln] : 0.0f;
        #pragma unroll
        for (int o = 4; o > 0; o >>= 1) t += __shfl_xor_sync(0xffffffffu, t, o);
        if (ln == 0) red[0] = t;
    }
    __syncthreads();
    float r = red[0];
    __syncthreads();
    return r;
}
__device__ __forceinline__ float blk_max256(float v, float* red) {
    #pragma unroll
    for (int o = 16; o > 0; o >>= 1) v = fmaxf(v, __shfl_xor_sync(0xffffffffu, v, o));
    int w = threadIdx.x >> 5, ln = threadIdx.x & 31;
    if (ln == 0) red[w] = v;
    __syncthreads();
    if (w == 0) {
        float t = (ln < 8) ? red[ln] : -3.0e38f;
        #pragma unroll
        for (int o = 4; o > 0; o >>= 1) t = fmaxf(t, __shfl_xor_sync(0xffffffffu, t, o));
        if (ln == 0) red[0] = t;
    }
    __syncthreads();
    float r = red[0];
    __syncthreads();
    return r;
}

// ==================== conversion kernels ====================
struct W6 { const float* W[6]; };

__global__ __launch_bounds__(256) void k_cvtw6(
    W6 ws, __half* __restrict__ O, int K, int N, size_t ostride)
{
    __shared__ float tile[32][33];
    const float* W = ws.W[blockIdx.z];
    __half* Oz = O + blockIdx.z * ostride;
    int k0 = blockIdx.x * 32, n0 = blockIdx.y * 32;
    int tx = threadIdx.x & 31, ty = threadIdx.x >> 5;
    #pragma unroll
    for (int j = 0; j < 32; j += 8)
        tile[ty + j][tx] = W[(size_t)(k0 + ty + j) * N + n0 + tx];
    __syncthreads();
    #pragma unroll
    for (int j = 0; j < 32; j += 8) {
        int n = n0 + ty + j, k = k0 + tx;
        Oz[(size_t)n * K + k] = __float2half(tile[tx][ty + j]);
    }
}

// ==================== fp16 mma.sync GEMM ====================
struct TcB {
    const __half* W[5];
    const float* b[5];
    float* C[5];
};

#define STG_BYTES 32768
#define MM_STG 3
#define MM_SMEM (MM_STG*STG_BYTES)

template <int ACT>
__global__ __launch_bounds__(256, 2) void k_wmma(
    const __half* __restrict__ A, TcB bt, int N, int K)
{
    extern __shared__ char smem[];
    const int z = blockIdx.z;
    const __half* Bw = bt.W[z];
    const float* bias = bt.b[z];
    float* C = bt.C[z];
    const int m0 = blockIdx.y * 128, n0 = blockIdx.x * 128;
    int tid = threadIdx.x, lane = tid & 31, wid = tid >> 5;
    int wm = wid & 3, wn = wid >> 2;
    uint32_t sb = s2u(smem);

    const int NIT = K >> 6;

    int lr = tid & 127;
    int half_ = tid >> 7;
    const char* gAr = (const char*)(A + (size_t)(m0 + lr) * K);
    const char* gBr = (const char*)(Bw + (size_t)(n0 + lr) * K);
    uint32_t stoff[4];
    uint32_t gcol[4];
    #pragma unroll
    for (int j = 0; j < 4; j++) {
        int c16 = half_ * 4 + j;
        stoff[j] = (uint32_t)(lr * 128 + ((c16 ^ (lr & 7)) << 4));
        gcol[j] = (uint32_t)(c16 << 4);
    }

    float acc[2][8][4];
    #pragma unroll
    for (int i = 0; i < 2; i++)
        #pragma unroll
        for (int j = 0; j < 8; j++)
            #pragma unroll
            for (int c = 0; c < 4; c++) acc[i][j][c] = 0.0f;

    auto issue = [&](int t) {
        int b = t % MM_STG;
        uint32_t base = sb + b * STG_BYTES;
        size_t off = (size_t)t * 128;
        #pragma unroll
        for (int j = 0; j < 4; j++) cp16(base + stoff[j], gAr + off + gcol[j]);
        #pragma unroll
        for (int j = 0; j < 4; j++) cp16(base + 16384 + stoff[j], gBr + off + gcol[j]);
        asm volatile("cp.async.commit_group;" ::: "memory");
    };
    issue(0); issue(1);

    int lrow = lane & 15, lk8 = lane >> 4, rxor = lrow & 7;
    uint32_t aRow = (uint32_t)((wm * 32 + lrow) * 128);
    uint32_t bRow = (uint32_t)((wn * 64 + lrow) * 128);
    uint32_t swz[4];
    #pragma unroll
    for (int kk = 0; kk < 4; kk++)
        swz[kk] = (uint32_t)((((kk * 2) + lk8) ^ rxor) << 4);

    for (int t = 0; t < NIT; t++) {
        if (t == NIT - 1) asm volatile("cp.async.wait_group 0;" ::: "memory");
        else              asm volatile("cp.async.wait_group 1;" ::: "memory");
        __syncthreads();
        if (t + 2 < NIT) issue(t + 2);

        int b = t % MM_STG;
        uint32_t aBase = sb + b * STG_BYTES + aRow;
        uint32_t bBase = sb + b * STG_BYTES + 16384 + bRow;
        #pragma unroll
        for (int kk = 0; kk < 4; kk++) {
            uint32_t ar[2][4], br[4][4];
            #pragma unroll
            for (int mf = 0; mf < 2; mf++)
                ldsm4(ar[mf], aBase + mf * (16 * 128) + swz[kk]);
            #pragma unroll
            for (int nf = 0; nf < 4; nf++)
                ldsm4(br[nf], bBase + nf * (16 * 128) + swz[kk]);
            #pragma unroll
            for (int mf = 0; mf < 2; mf++)
                #pragma unroll
                for (int ns = 0; ns < 8; ns++)
                    mma_f16(acc[mf][ns], ar[mf],
                            br[ns >> 1][ns & 1], br[ns >> 1][(ns & 1) + 2]);
        }
    }

    int erow = lane >> 2, ecol = (lane & 3) * 2;
    #pragma unroll
    for (int mf = 0; mf < 2; mf++) {
        int r0 = m0 + wm * 32 + mf * 16 + erow;
        #pragma unroll
        for (int ns = 0; ns < 8; ns++) {
            int cc = n0 + wn * 64 + ns * 8 + ecol;
            float b0 = bias[cc], b1 = bias[cc + 1];
            float v0 = acc[mf][ns][0] + b0;
            float v1 = acc[mf][ns][1] + b1;
            float v2 = acc[mf][ns][2] + b0;
            float v3 = acc[mf][ns][3] + b1;
            if (ACT == 0) {
                *reinterpret_cast<float2*>(&C[(size_t)r0 * N + cc])       = make_float2(v0, v1);
                *reinterpret_cast<float2*>(&C[(size_t)(r0 + 8) * N + cc]) = make_float2(v2, v3);
            } else {
                if (ACT == 1) {
                    v0 = 0.5f * v0 * (1.0f + erff(v0 * 0.70710678118654752440f));
                    v1 = 0.5f * v1 * (1.0f + erff(v1 * 0.70710678118654752440f));
                    v2 = 0.5f * v2 * (1.0f + erff(v2 * 0.70710678118654752440f));
                    v3 = 0.5f * v3 * (1.0f + erff(v3 * 0.70710678118654752440f));
                }
                __half* C16 = (__half*)C;
                *reinterpret_cast<__half2*>(&C16[(size_t)r0 * N + cc]) =
                    __halves2half2(__float2half(v0), __float2half(v1));
                *reinterpret_cast<__half2*>(&C16[(size_t)(r0 + 8) * N + cc]) =
                    __halves2half2(__float2half(v2), __float2half(v3));
            }
        }
    }
}

// ==================== split-K fp16 GEMM (fp32 partial outputs) ====================
// grid.z = K-split index; each z computes C_z = A[:, zKs:(z+1)Ks] @ W[:, same]^T
// bias added only in slice 0. Row strides remain Kt.
struct P4 { float* C[4]; };

__global__ __launch_bounds__(256, 2) void k_wmmas(
    const __half* __restrict__ A, const __half* __restrict__ Bw,
    const float* __restrict__ bias, P4 ps, int N, int Kt)
{
    extern __shared__ char smem[];
    const int z = blockIdx.z, ns = gridDim.z;
    const int Ks = Kt / ns;
    float* C = ps.C[z];
    const int m0 = blockIdx.y * 128, n0 = blockIdx.x * 128;
    int tid = threadIdx.x, lane = tid & 31, wid = tid >> 5;
    int wm = wid & 3, wn = wid >> 2;
    uint32_t sb = s2u(smem);

    const int NIT = Ks >> 6;

    int lr = tid & 127;
    int half_ = tid >> 7;
    const char* gAr = (const char*)(A + (size_t)(m0 + lr) * Kt + (size_t)z * Ks);
    const char* gBr = (const char*)(Bw + (size_t)(n0 + lr) * Kt + (size_t)z * Ks);
    uint32_t stoff[4];
    uint32_t gcol[4];
    #pragma unroll
    for (int j = 0; j < 4; j++) {
        int c16 = half_ * 4 + j;
        stoff[j] = (uint32_t)(lr * 128 + ((c16 ^ (lr & 7)) << 4));
        gcol[j] = (uint32_t)(c16 << 4);
    }

    float acc[2][8][4];
    #pragma unroll
    for (int i = 0; i < 2; i++)
        #pragma unroll
        for (int j = 0; j < 8; j++)
            #pragma unroll
            for (int c = 0; c < 4; c++) acc[i][j][c] = 0.0f;

    auto issue = [&](int t) {
        int b = t % MM_STG;
        uint32_t base = sb + b * STG_BYTES;
        size_t off = (size_t)t * 128;
        #pragma unroll
        for (int j = 0; j < 4; j++) cp16(base + stoff[j], gAr + off + gcol[j]);
        #pragma unroll
        for (int j = 0; j < 4; j++) cp16(base + 16384 + stoff[j], gBr + off + gcol[j]);
        asm volatile("cp.async.commit_group;" ::: "memory");
    };
    issue(0); issue(1);

    int lrow = lane & 15, lk8 = lane >> 4, rxor = lrow & 7;
    uint32_t aRow = (uint32_t)((wm * 32 + lrow) * 128);
    uint32_t bRow = (uint32_t)((wn * 64 + lrow) * 128);
    uint32_t swz[4];
    #pragma unroll
    for (int kk = 0; kk < 4; kk++)
        swz[kk] = (uint32_t)((((kk * 2) + lk8) ^ rxor) << 4);

    for (int t = 0; t < NIT; t++) {
        if (t == NIT - 1) asm volatile("cp.async.wait_group 0;" ::: "memory");
        else              asm volatile("cp.async.wait_group 1;" ::: "memory");
        __syncthreads();
        if (t + 2 < NIT) issue(t + 2);

        int b = t % MM_STG;
        uint32_t aBase = sb + b * STG_BYTES + aRow;
        uint32_t bBase = sb + b * STG_BYTES + 16384 + bRow;
        #pragma unroll
        for (int kk = 0; kk < 4; kk++) {
            uint32_t ar[2][4], br[4][4];
            #pragma unroll
            for (int mf = 0; mf < 2; mf++)
                ldsm4(ar[mf], aBase + mf * (16 * 128) + swz[kk]);
            #pragma unroll
            for (int nf = 0; nf < 4; nf++)
                ldsm4(br[nf], bBase + nf * (16 * 128) + swz[kk]);
            #pragma unroll
            for (int mf = 0; mf < 2; mf++)
                #pragma unroll
                for (int ns = 0; ns < 8; ns++)
                    mma_f16(acc[mf][ns], ar[mf],
                            br[ns >> 1][ns & 1], br[ns >> 1][(ns & 1) + 2]);
        }
    }

    int erow = lane >> 2, ecol = (lane & 3) * 2;
    #pragma unroll
    for (int mf = 0; mf < 2; mf++) {
        int r0 = m0 + wm * 32 + mf * 16 + erow;
        #pragma unroll
        for (int ns = 0; ns < 8; ns++) {
            int cc = n0 + wn * 64 + ns * 8 + ecol;
            float b0 = (z == 0) ? bias[cc] : 0.0f;
            float b1 = (z == 0) ? bias[cc + 1] : 0.0f;
            *reinterpret_cast<float2*>(&C[(size_t)r0 * N + cc]) =
                make_float2(acc[mf][ns][0] + b0, acc[mf][ns][1] + b1);
            *reinterpret_cast<float2*>(&C[(size_t)(r0 + 8) * N + cc]) =
                make_float2(acc[mf][ns][2] + b0, acc[mf][ns][3] + b1);
        }
    }
}

// ==================== non-GEMM kernels ====================
__global__ __launch_bounds__(256) void k_embed(
    const int* __restrict__ ids, const float* __restrict__ wemb,
    const float* __restrict__ pemb, const float* __restrict__ lns,
    const float* __restrict__ lnb, float* __restrict__ xout,
    __half* __restrict__ x16)
{
    __shared__ float red[32];
    int row = blockIdx.x;
    int tid = threadIdx.x;
    int s = row & (SS - 1);
    int id = ids[row];
    const float* we = wemb + (size_t)id * HID;
    const float* pe = pemb + (size_t)s * HID;
    float v0 = we[tid]       + pe[tid];
    float v1 = we[tid + 256] + pe[tid + 256];
    float v2 = we[tid + 512] + pe[tid + 512];
    float mean = blk_sum256(v0 + v1 + v2, red) * (1.0f / HID);
    v0 -= mean; v1 -= mean; v2 -= mean;
    float var = blk_sum256(v0*v0 + v1*v1 + v2*v2, red) * (1.0f / HID);
    float r = rsqrtf(var + 1e-5f);
    size_t base = (size_t)row * HID;
    float o0 = v0 * r * lns[tid]       + lnb[tid];
    float o1 = v1 * r * lns[tid + 256] + lnb[tid + 256];
    float o2 = v2 * r * lns[tid + 512] + lnb[tid + 512];
    xout[base + tid]       = o0;
    xout[base + tid + 256] = o1;
    xout[base + tid + 512] = o2;
    x16[base + tid]        = __float2half(o0);
    x16[base + tid + 256]  = __float2half(o1);
    x16[base + tid + 512]  = __float2half(o2);
}

// residual add + LN summing NP partials
struct AP { const float* p[4]; };

template <int NP>
__global__ __launch_bounds__(256) void k_addlnP(
    AP ap, const float* __restrict__ lns, const float* __restrict__ lnb,
    float* __restrict__ x, __half* __restrict__ x16)
{
    __shared__ float red[32];
    int row = blockIdx.x;
    int tid = threadIdx.x;
    size_t base = (size_t)row * HID;
    float v0 = x[base + tid];
    float v1 = x[base + tid + 256];
    float v2 = x[base + tid + 512];
    #pragma unroll
    for (int i = 0; i < NP; i++) {
        v0 += ap.p[i][base + tid];
        v1 += ap.p[i][base + tid + 256];
        v2 += ap.p[i][base + tid + 512];
    }
    float mean = blk_sum256(v0 + v1 + v2, red) * (1.0f / HID);
    v0 -= mean; v1 -= mean; v2 -= mean;
    float var = blk_sum256(v0*v0 + v1*v1 + v2*v2, red) * (1.0f / HID);
    float r = rsqrtf(var + 1e-5f);
    float o0 = v0 * r * lns[tid]       + lnb[tid];
    float o1 = v1 * r * lns[tid + 256] + lnb[tid + 256];
    float o2 = v2 * r * lns[tid + 512] + lnb[tid + 512];
    x[base + tid]       = o0;
    x[base + tid + 256] = o1;
    x[base + tid + 512] = o2;
    x16[base + tid]       = __float2half(o0);
    x16[base + tid + 256] = __float2half(o1);
    x16[base + tid + 512] = __float2half(o2);
}

__global__ __launch_bounds__(256) void k_qg0(
    const float* __restrict__ x, const float* __restrict__ Wg,
    const float* __restrict__ bg, float* __restrict__ outq)
{
    int b = blockIdx.y;
    int n = blockIdx.x * 256 + threadIdx.x;
    __shared__ float xs[HID];
    for (int i = threadIdx.x; i < HID; i += 256) xs[i] = x[(size_t)b * SS * HID + i];
    __syncthreads();
    float acc = bg[n];
    for (int kk = 0; kk < HID; kk++) acc = fmaf(xs[kk], Wg[(size_t)kk * HID + n], acc);
    outq[b * HID + n] = acc;
}

// ---- banded attention: cp.async pipeline + f32x2 packed FMA + tile softmax ----
#define KT 32
#define NTILE 24
#define BAND_SMEM (49152 + 32768 + 256 + 256 + 768)

__global__ __launch_bounds__(256) void k_band(
    const float* __restrict__ q, const float* __restrict__ k,
    const float* __restrict__ v, const float* __restrict__ kg,
    const float* __restrict__ vg, const int* __restrict__ am,
    __half* __restrict__ out)
{
    extern __shared__ char sm[];
    float* scs = (float*)(sm + 49152);
    float* kg0 = (float*)(sm + 81920);
    float* vg0 = (float*)(sm + 82176);
    unsigned char* kval = (unsigned char*)(sm + 82432);
    uint32_t sb = s2u(sm);

    int c = blockIdx.x, h = blockIdx.y, b = blockIdx.z;
    int p = threadIdx.x;
    int tid = threadIdx.x;
    int qpos = c * WW + p;
    int cstart = (c - 1) * WW;

    if (tid < DH) {
        kg0[tid] = kg[(size_t)(b * SS) * HID + h * DH + tid];
        vg0[tid] = vg[(size_t)(b * SS) * HID + h * DH + tid];
    }
    for (int j = tid; j < 3 * WW; j += 256) {
        int kp = cstart + j;
        kval[j] = (kp > 0 && kp < SS && am[b * SS + kp] > 0) ? 1 : 0;
    }

    int jj0 = tid >> 4,          dd0 = tid & 15;
    int jj1 = (tid + 256) >> 4,  dd1 = tid & 15;
    uint32_t st0 = (uint32_t)(jj0 * 256 + dd0 * 16);
    uint32_t st1 = (uint32_t)(jj1 * 256 + dd1 * 16);

    auto issue = [&](int t) {
        int s = t % 3;
        uint32_t base = sb + s * 16384;
        int kt0 = t * KT;
        int kp0 = min(max(cstart + kt0 + jj0, 0), SS - 1);
        int kp1 = min(max(cstart + kt0 + jj1, 0), SS - 1);
        size_t g0 = (size_t)(b * SS + kp0) * HID + h * DH + dd0 * 4;
        size_t g1 = (size_t)(b * SS + kp1) * HID + h * DH + dd1 * 4;
        cp16(base + st0, k + g0);
        cp16(base + st1, k + g1);
        cp16(base + 8192 + st0, v + g0);
        cp16(base + 8192 + st1, v + g1);
        asm volatile("cp.async.commit_group;" ::: "memory");
    };
    issue(0); issue(1);

    // q packed into 32 u64
    unsigned long long qv2[32];
    {
        const float4* qp4 = reinterpret_cast<const float4*>(
            q + (size_t)(b * SS + qpos) * HID + h * DH);
        #pragma unroll
        for (int i = 0; i < 16; i++) {
            float4 qf = qp4[i];
            qv2[2 * i]     = pk2(qf.x, qf.y);
            qv2[2 * i + 1] = pk2(qf.z, qf.w);
        }
    }
    __syncthreads();   // kg0/vg0/kval ready

    // init online softmax with the global (CLS key) column
    float m;
    {
        unsigned long long a0 = 0ULL, a1 = 0ULL, a2 = 0ULL, a3 = 0ULL;
        const ulonglong2* g8 = reinterpret_cast<const ulonglong2*>(kg0);
        #pragma unroll
        for (int i = 0; i < 16; i += 2) {
            ulonglong2 ka = g8[i], kb = g8[i + 1];
            fma2(a0, qv2[2*i],     ka.x);
            fma2(a1, qv2[2*i + 1], ka.y);
            fma2(a2, qv2[2*i + 2], kb.x);
            fma2(a3, qv2[2*i + 3], kb.y);
        }
        float2 f0 = upk2(a0), f1 = upk2(a1), f2 = upk2(a2), f3 = upk2(a3);
        m = ((f0.x + f0.y) + (f1.x + f1.y) + (f2.x + f2.y) + (f3.x + f3.y)) * 0.125f;
    }
    float l = 1.0f;
    unsigned long long accv2[32];
    #pragma unroll
    for (int i = 0; i < 32; i++) accv2[i] = pk2(vg0[2 * i], vg0[2 * i + 1]);

    for (int t = 0; t < NTILE; t++) {
        if (t == NTILE - 1) asm volatile("cp.async.wait_group 0;" ::: "memory");
        else                asm volatile("cp.async.wait_group 1;" ::: "memory");
        __syncthreads();
        if (t + 2 < NTILE) issue(t + 2);

        int kt0 = t * KT;
        const char* kb = sm + (t % 3) * 16384;
        const char* vb = kb + 8192;

        int jlo = max(p - kt0, 0);
        int jhi = min(p + 2 * WW - kt0, KT - 1);

        // pass 1: scores via packed fma, tile max
        float tmax = -3.0e38f;
        for (int jj = jlo; jj <= jhi; jj++) {
            int j = kt0 + jj;
            if (!kval[j]) continue;
            const ulonglong2* kp8 = (const ulonglong2*)(kb + jj * 256);
            unsigned long long a0 = 0ULL, a1 = 0ULL, a2 = 0ULL, a3 = 0ULL;
            #pragma unroll
            for (int i = 0; i < 16; i += 2) {
                ulonglong2 ka = kp8[i], kbv = kp8[i + 1];
                fma2(a0, qv2[2*i],     ka.x);
                fma2(a1, qv2[2*i + 1], ka.y);
                fma2(a2, qv2[2*i + 2], kbv.x);
                fma2(a3, qv2[2*i + 3], kbv.y);
            }
            float2 f0 = upk2(a0), f1 = upk2(a1), f2 = upk2(a2), f3 = upk2(a3);
            float sc = ((f0.x + f0.y) + (f1.x + f1.y) + (f2.x + f2.y) + (f3.x + f3.y)) * 0.125f;
            scs[jj * 256 + tid] = sc;
            tmax = fmaxf(tmax, sc);
        }
        if (tmax > -1.0e37f) {
            if (tmax > m) {
                float fac = __expf(m - tmax);
                l *= fac;
                unsigned long long f2p = pk2(fac, fac);
                #pragma unroll
                for (int i = 0; i < 32; i++) accv2[i] = mul2(accv2[i], f2p);
                m = tmax;
            }
            // pass 2: single exp per key + packed PV accumulate
            for (int jj = jlo; jj <= jhi; jj++) {
                int j = kt0 + jj;
                if (!kval[j]) continue;
                float w = __expf(scs[jj * 256 + tid] - m);
                l += w;
                unsigned long long w2 = pk2(w, w);
                const ulonglong2* vp8 = (const ulonglong2*)(vb + jj * 256);
                #pragma unroll
                for (int i = 0; i < 16; i++) {
                    ulonglong2 vv = vp8[i];
                    fma2(accv2[2 * i],     w2, vv.x);
                    fma2(accv2[2 * i + 1], w2, vv.y);
                }
            }
        }
    }
    float inv = 1.0f / l;
    __half* op = out + (size_t)(b * SS + qpos) * HID + h * DH;
    #pragma unroll
    for (int i = 0; i < 16; i++) {
        float2 fa = upk2(accv2[2 * i]);
        float2 fb = upk2(accv2[2 * i + 1]);
        *reinterpret_cast<__half2*>(op + i * 4) =
            __floats2half2_rn(fa.x * inv, fa.y * inv);
        *reinterpret_cast<__half2*>(op + i * 4 + 2) =
            __floats2half2_rn(fb.x * inv, fb.y * inv);
    }
}

// ---- global CLS row: split over 16 seq chunks (f32x2), then merge ----
__global__ __launch_bounds__(256) void k_glob1(
    const float* __restrict__ qg0, const float* __restrict__ kg,
    const float* __restrict__ vg, const int* __restrict__ am,
    float* __restrict__ gm, float* __restrict__ gl, float* __restrict__ go)
{
    int c = blockIdx.x;             // 0..15
    int bh = blockIdx.y;            // 0..23
    int b = bh / HEADS, h = bh % HEADS;
    int tid = threadIdx.x;
    __shared__ __align__(16) float q0[DH];
    __shared__ float sc[256];
    __shared__ float red[32];
    __shared__ __align__(16) unsigned long long part2[8][32];

    if (tid < DH) q0[tid] = qg0[b * HID + h * DH + tid];
    __syncthreads();

    int j = c * 256 + tid;
    float sv = -1e9f;
    if (am[b * SS + j] > 0) {
        const ulonglong2* kr8 = reinterpret_cast<const ulonglong2*>(
            kg + (size_t)(b * SS + j) * HID + h * DH);
        const ulonglong2* q8 = reinterpret_cast<const ulonglong2*>(q0);
        unsigned long long a0 = 0ULL, a1 = 0ULL, a2 = 0ULL, a3 = 0ULL;
        #pragma unroll
        for (int i = 0; i < 16; i += 2) {
            ulonglong2 ka = kr8[i], kbv = kr8[i + 1];
            ulonglong2 qa = q8[i],  qb  = q8[i + 1];
            fma2(a0, qa.x, ka.x);
            fma2(a1, qa.y, ka.y);
            fma2(a2, qb.x, kbv.x);
            fma2(a3, qb.y, kbv.y);
        }
        float2 f0 = upk2(a0), f1 = upk2(a1), f2 = upk2(a2), f3 = upk2(a3);
        sv = ((f0.x + f0.y) + (f1.x + f1.y) + (f2.x + f2.y) + (f3.x + f3.y)) * 0.125f;
    }
    float mc = blk_max256(sv, red);
    float w = (sv > -1.0e8f) ? __expf(sv - mc) : 0.0f;
    sc[tid] = w;
    float lc = blk_sum256(w, red);
    __syncthreads();

    // PV: thread owns d-pair (tid&31), group g = tid>>5 covers 32 keys
    int d2 = tid & 31, g = tid >> 5;
    unsigned long long acc2 = 0ULL;
    #pragma unroll 4
    for (int jj = g * 32; jj < g * 32 + 32; jj++) {
        unsigned long long w2 = pk2(sc[jj], sc[jj]);
        const unsigned long long* vr = reinterpret_cast<const unsigned long long*>(
            vg + (size_t)(b * SS + c * 256 + jj) * HID + h * DH);
        fma2(acc2, w2, vr[d2]);
    }
    part2[g][d2] = acc2;
    __syncthreads();
    if (tid < 32) {
        unsigned long long s = part2[0][tid];
        float2 t = upk2(s);
        #pragma unroll
        for (int gg = 1; gg < 8; gg++) {
            float2 u = upk2(part2[gg][tid]);
            t.x += u.x; t.y += u.y;
        }
        go[((size_t)bh * 16 + c) * DH + 2 * tid]     = t.x;
        go[((size_t)bh * 16 + c) * DH + 2 * tid + 1] = t.y;
    }
    if (tid == 0) { gm[bh * 16 + c] = mc; gl[bh * 16 + c] = lc; }
}

__global__ __launch_bounds__(64) void k_glob2(
    const float* __restrict__ gm, const float* __restrict__ gl,
    const float* __restrict__ go, __half* __restrict__ out)
{
    int bh = blockIdx.x;
    int b = bh / HEADS, h = bh % HEADS;
    int d = threadIdx.x;
    float mstar = -3.0e38f;
    #pragma unroll
    for (int c = 0; c < 16; c++) mstar = fmaxf(mstar, gm[bh * 16 + c]);
    float lsum = 0.0f, osum = 0.0f;
    #pragma unroll
    for (int c = 0; c < 16; c++) {
        float e = __expf(gm[bh * 16 + c] - mstar);
        lsum += gl[bh * 16 + c] * e;
        osum += go[((size_t)bh * 16 + c) * DH + d] * e;
    }
    out[(size_t)(b * SS) * HID + h * DH + d] = __float2half(osum / lsum);
}

// ---- classifier head: 64-label tiles x 4-way K split ----
__global__ __launch_bounds__(256) void k_head(
    const float* __restrict__ x, const float* __restrict__ hw,
    const float* __restrict__ hb, float* __restrict__ out)
{
    int b = blockIdx.y;
    int n0 = blockIdx.x * 64;
    int lbl = threadIdx.x & 63;
    int kc = threadIdx.x >> 6;          // 0..3
    __shared__ float xs[HID];
    __shared__ float partial[4][64];
    for (int i = threadIdx.x; i < HID; i += 256) xs[i] = x[(size_t)b * SS * HID + i];
    __syncthreads();
    int n = n0 + lbl;
    float acc = 0.0f;
    if (n < NLAB) {
        #pragma unroll 4
        for (int kk = kc * 192; kk < kc * 192 + 192; kk++)
            acc = fmaf(xs[kk], hw[(size_t)kk * NLAB + n], acc);
    }
    partial[kc][lbl] = acc;
    __syncthreads();
    if (threadIdx.x < 64) {
        int nn = n0 + threadIdx.x;
        if (nn < NLAB)
            out[(size_t)b * NLAB + nn] = partial[0][threadIdx.x] + partial[1][threadIdx.x]
                + partial[2][threadIdx.x] + partial[3][threadIdx.x] + hb[nn];
    }
}

// ==================== orchestration ====================
extern "C" void kernel_launch(void* const* d_in, const int* in_sizes, int n_in,
                              void* d_out, int out_size)
{
    const int*   ids  = (const int*)d_in[0];
    const int*   am   = (const int*)d_in[1];
    const float* wemb = (const float*)d_in[2];
    const float* pemb = (const float*)d_in[3];
    const float* elns = (const float*)d_in[4];
    const float* elnb = (const float*)d_in[5];
    const float* Wq   = (const float*)d_in[6];
    const float* bq   = (const float*)d_in[7];
    const float* Wk   = (const float*)d_in[8];
    const float* bk   = (const float*)d_in[9];
    const float* Wv   = (const float*)d_in[10];
    const float* bv   = (const float*)d_in[11];
    const float* Wqg  = (const float*)d_in[12];
    const float* bqg  = (const float*)d_in[13];
    const float* Wkg  = (const float*)d_in[14];
    const float* bkg  = (const float*)d_in[15];
    const float* Wvg  = (const float*)d_in[16];
    const float* bvg  = (const float*)d_in[17];
    const float* Wo   = (const float*)d_in[18];
    const float* bo   = (const float*)d_in[19];
    const float* ln1s = (const float*)d_in[20];
    const float* ln1b = (const float*)d_in[21];
    const float* W1   = (const float*)d_in[22];
    const float* b1   = (const float*)d_in[23];
    const float* W2   = (const float*)d_in[24];
    const float* b2   = (const float*)d_in[25];
    const float* ln2s = (const float*)d_in[26];
    const float* ln2b = (const float*)d_in[27];
    const float* hW   = (const float*)d_in[28];
    const float* hb   = (const float*)d_in[29];
    float* out = (float*)d_out;

    float *px, *pq, *pk, *pv, *pkg, *pvg, *ptmp, *pqg0, *pgm, *pgl, *pgo;
    __half *pwt, *pw1t, *pw2t, *pab, *pab2;
    cudaGetSymbolAddress((void**)&px,   g_x);
    cudaGetSymbolAddress((void**)&pq,   g_q);
    cudaGetSymbolAddress((void**)&pk,   g_k);
    cudaGetSymbolAddress((void**)&pv,   g_v);
    cudaGetSymbolAddress((void**)&pkg,  g_kg);
    cudaGetSymbolAddress((void**)&pvg,  g_vg);
    cudaGetSymbolAddress((void**)&ptmp, g_tmp);
    cudaGetSymbolAddress((void**)&pqg0, g_qg0);
    cudaGetSymbolAddress((void**)&pgm,  g_gm);
    cudaGetSymbolAddress((void**)&pgl,  g_gl);
    cudaGetSymbolAddress((void**)&pgo,  g_go);
    cudaGetSymbolAddress((void**)&pwt,  g_wt);
    cudaGetSymbolAddress((void**)&pw1t, g_w1t);
    cudaGetSymbolAddress((void**)&pw2t, g_w2t);
    cudaGetSymbolAddress((void**)&pab,  g_ab);
    cudaGetSymbolAddress((void**)&pab2, g_ab2);

    cudaFuncSetAttribute(k_wmma<0>, cudaFuncAttributeMaxDynamicSharedMemorySize, MM_SMEM);
    cudaFuncSetAttribute(k_wmma<1>, cudaFuncAttributeMaxDynamicSharedMemorySize, MM_SMEM);
    cudaFuncSetAttribute(k_wmmas, cudaFuncAttributeMaxDynamicSharedMemorySize, MM_SMEM);
    cudaFuncSetAttribute(k_band, cudaFuncAttributeMaxDynamicSharedMemorySize, BAND_SMEM);

    const size_t WSTRIDE = (size_t)HID * HID;

    // ---- weight conversions (batched) ----
    for (int l = 0; l < 2; l++) {
        size_t ow  = (size_t)l * HID * HID;
        size_t ow1 = (size_t)l * HID * FFNDIM;
        W6 ws;
        ws.W[0] = Wq + ow; ws.W[1] = Wk + ow; ws.W[2] = Wv + ow;
        ws.W[3] = Wkg + ow; ws.W[4] = Wvg + ow; ws.W[5] = Wo + ow;
        k_cvtw6<<<dim3(HID / 32, HID / 32, 6), 256>>>(
            ws, pwt + (size_t)(l * 6) * WSTRIDE, HID, HID, WSTRIDE);
        W6 w1; w1.W[0] = W1 + ow1;
        k_cvtw6<<<dim3(HID / 32, FFNDIM / 32, 1), 256>>>(
            w1, pw1t + (size_t)l * FFNDIM * HID, HID, FFNDIM, 0);
        W6 w2; w2.W[0] = W2 + ow1;
        k_cvtw6<<<dim3(FFNDIM / 32, HID / 32, 1), 256>>>(
            w2, pw2t + (size_t)l * HID * FFNDIM, FFNDIM, HID, 0);
    }

    k_embed<<<NTOK, 256>>>(ids, wemb, pemb, elns, elnb, px, pab2);

    for (int l = 0; l < 2; l++) {
        size_t ow  = (size_t)l * HID * HID;
        size_t ob  = (size_t)l * HID;
        size_t ob1 = (size_t)l * FFNDIM;
        const __half* wl = pwt + (size_t)(l * 6) * WSTRIDE;

        // 5 projections batched (input pab2 = fp16 of x), fp32 outputs
        {
            TcB b5;
            b5.W[0] = wl + 0 * WSTRIDE; b5.b[0] = bq  + ob; b5.C[0] = pq;
            b5.W[1] = wl + 1 * WSTRIDE; b5.b[1] = bk  + ob; b5.C[1] = pk;
            b5.W[2] = wl + 2 * WSTRIDE; b5.b[2] = bv  + ob; b5.C[2] = pv;
            b5.W[3] = wl + 3 * WSTRIDE; b5.b[3] = bkg + ob; b5.C[3] = pkg;
            b5.W[4] = wl + 4 * WSTRIDE; b5.b[4] = bvg + ob; b5.C[4] = pvg;
            k_wmma<0><<<dim3(HID / 128, NTOK / 128, 5), 256, MM_SMEM>>>(pab2, b5, HID, HID);
        }
        k_qg0<<<dim3(3, BB), 256>>>(px, Wqg + ow, bqg + ob, pqg0);

        // attention writes fp16 directly into pab2
        k_band<<<dim3(NC, HEADS, BB), 256, BAND_SMEM>>>(pq, pk, pv, pkg, pvg, am, pab2);
        k_glob1<<<dim3(16, BB * HEADS), 256>>>(pqg0, pkg, pvg, am, pgm, pgl, pgo);
        k_glob2<<<BB * HEADS, 64>>>(pgm, pgl, pgo, pab2);

        // attn @ Wo : split-K2 (q/k/v buffers now dead -> partials)
        {
            P4 ps; ps.C[0] = ptmp; ps.C[1] = pq; ps.C[2] = ptmp; ps.C[3] = ptmp;
            k_wmmas<<<dim3(HID / 128, NTOK / 128, 2), 256, MM_SMEM>>>(
                pab2, wl + 5 * WSTRIDE, bo + ob, ps, HID, HID);
            AP ap; ap.p[0] = ptmp; ap.p[1] = pq; ap.p[2] = ptmp; ap.p[3] = ptmp;
            k_addlnP<2><<<NTOK, 256>>>(ap, ln1s + ob, ln1b + ob, px, pab2);
        }

        // FFN: W1 writes GELU'd fp16 directly into pab
        {
            TcB bw1; bw1.W[0] = pw1t + (size_t)l * FFNDIM * HID; bw1.b[0] = b1 + ob1;
            bw1.C[0] = (float*)pab;
            bw1.W[1] = bw1.W[0]; bw1.b[1] = bw1.b[0]; bw1.C[1] = bw1.C[0];
            bw1.W[2] = bw1.W[0]; bw1.b[2] = bw1.b[0]; bw1.C[2] = bw1.C[0];
            bw1.W[3] = bw1.W[0]; bw1.b[3] = bw1.b[0]; bw1.C[3] = bw1.C[0];
            bw1.W[4] = bw1.W[0]; bw1.b[4] = bw1.b[0]; bw1.C[4] = bw1.C[0];
            k_wmma<1><<<dim3(FFNDIM / 128, NTOK / 128, 1), 256, MM_SMEM>>>(pab2, bw1, FFNDIM, HID);
        }
        // W2 : split-K4
        {
            P4 ps; ps.C[0] = ptmp; ps.C[1] = pq; ps.C[2] = pk; ps.C[3] = pv;
            k_wmmas<<<dim3(HID / 128, NTOK / 128, 4), 256, MM_SMEM>>>(
                pab, pw2t + (size_t)l * HID * FFNDIM, b2 + ob, ps, HID, FFNDIM);
            AP ap; ap.p[0] = ptmp; ap.p[1] = pq; ap.p[2] = pk; ap.p[3] = pv;
            k_addlnP<4><<<NTOK, 256>>>(ap, ln2s + ob, ln2b + ob, px, pab2);
        }
    }

    k_head<<<dim3((NLAB + 63) / 64, BB), 256>>>(px, hW, hb, out);
}

// round 16
// speedup vs baseline: 1.2372x; 1.2372x over previous
#include <cuda_runtime.h>
#include <cuda_fp16.h>
#include <math.h>
#include <stdint.h>

#define HID 768
#define HEADS 12
#define DH 64
#define WW 256
#define NC 16
#define FFNDIM 3072
#define NLAB 8921
#define BB 2
#define SS 4096
#define NTOK (BB*SS)

// -------- scratch (device globals; no allocation allowed) --------
__device__ __align__(256) float g_x[NTOK*HID];
__device__ __align__(256) float g_q[NTOK*HID];
__device__ __align__(256) float g_k[NTOK*HID];
__device__ __align__(256) float g_v[NTOK*HID];
__device__ __align__(256) float g_kg[NTOK*HID];
__device__ __align__(256) float g_vg[NTOK*HID];
__device__ __align__(256) float g_tmp[NTOK*HID];
__device__ __align__(256) float g_qg0[BB*HID];
__device__ __align__(256) float g_gm[BB*HEADS*16];
__device__ __align__(256) float g_gl[BB*HEADS*16];
__device__ __align__(256) float g_go[BB*HEADS*16*DH];
__device__ __align__(256) __half g_wt[(size_t)2*6*HID*HID];
__device__ __align__(256) __half g_w1t[(size_t)2*FFNDIM*HID];
__device__ __align__(256) __half g_w2t[(size_t)2*HID*FFNDIM];
__device__ __align__(256) __half g_ab[(size_t)NTOK*FFNDIM];   // FFN intermediate fp16
__device__ __align__(256) __half g_ab2[(size_t)NTOK*HID];     // HID-wide fp16 activations

// ==================== small helpers ====================
__device__ __forceinline__ uint32_t s2u(const void* p) {
    uint32_t a;
    asm("{ .reg .u64 t; cvta.to.shared.u64 t, %1; cvt.u32.u64 %0, t; }" : "=r"(a) : "l"(p));
    return a;
}
__device__ __forceinline__ void cp16(uint32_t s, const void* g) {
    asm volatile("cp.async.cg.shared.global [%0], [%1], 16;" :: "r"(s), "l"(g));
}
__device__ __forceinline__ void ldsm4(uint32_t* r, uint32_t addr) {
    asm volatile("ldmatrix.sync.aligned.m8n8.x4.shared.b16 {%0,%1,%2,%3}, [%4];"
        : "=r"(r[0]), "=r"(r[1]), "=r"(r[2]), "=r"(r[3]) : "r"(addr));
}
__device__ __forceinline__ void mma_f16(float* d, const uint32_t* a, uint32_t b0, uint32_t b1) {
    asm volatile(
        "mma.sync.aligned.m16n8k16.row.col.f32.f16.f16.f32 "
        "{%0,%1,%2,%3}, {%4,%5,%6,%7}, {%8,%9}, {%0,%1,%2,%3};"
        : "+f"(d[0]), "+f"(d[1]), "+f"(d[2]), "+f"(d[3])
        : "r"(a[0]), "r"(a[1]), "r"(a[2]), "r"(a[3]), "r"(b0), "r"(b1));
}
// ---- packed fp32x2 (exact per-lane fp32 ops) ----
__device__ __forceinline__ void fma2(unsigned long long& d, unsigned long long a, unsigned long long b) {
    asm("fma.rn.f32x2 %0, %1, %2, %0;" : "+l"(d) : "l"(a), "l"(b));
}
__device__ __forceinline__ unsigned long long mul2(unsigned long long a, unsigned long long b) {
    unsigned long long r;
    asm("mul.rn.f32x2 %0, %1, %2;" : "=l"(r) : "l"(a), "l"(b));
    return r;
}
__device__ __forceinline__ unsigned long long pk2(float lo, float hi) {
    unsigned long long r;
    asm("mov.b64 %0, {%1, %2};" : "=l"(r) : "f"(lo), "f"(hi));
    return r;
}
__device__ __forceinline__ float2 upk2(unsigned long long v) {
    float2 f;
    asm("mov.b64 {%0, %1}, %2;" : "=f"(f.x), "=f"(f.y) : "l"(v));
    return f;
}

// -------- block reduction helpers (256 threads) --------
__device__ __forceinline__ float blk_sum256(float v, float* red) {
    #pragma unroll
    for (int o = 16; o > 0; o >>= 1) v += __shfl_xor_sync(0xffffffffu, v, o);
    int w = threadIdx.x >> 5, ln = threadIdx.x & 31;
    if (ln == 0) red[w] = v;
    __syncthreads();
    if (w == 0) {
        float t = (ln < 8) ? red[ln] : 0.0f;
        #pragma unroll
        for (int o = 4; o > 0; o >>= 1) t += __shfl_xor_sync(0xffffffffu, t, o);
        if (ln == 0) red[0] = t;
    }
    __syncthreads();
    float r = red[0];
    __syncthreads();
    return r;
}
__device__ __forceinline__ float blk_max256(float v, float* red) {
    #pragma unroll
    for (int o = 16; o > 0; o >>= 1) v = fmaxf(v, __shfl_xor_sync(0xffffffffu, v, o));
    int w = threadIdx.x >> 5, ln = threadIdx.x & 31;
    if (ln == 0) red[w] = v;
    __syncthreads();
    if (w == 0) {
        float t = (ln < 8) ? red[ln] : -3.0e38f;
        #pragma unroll
        for (int o = 4; o > 0; o >>= 1) t = fmaxf(t, __shfl_xor_sync(0xffffffffu, t, o));
        if (ln == 0) red[0] = t;
    }
    __syncthreads();
    float r = red[0];
    __syncthreads();
    return r;
}

// ==================== conversion kernels ====================
struct W6 { const float* W[6]; };

__global__ __launch_bounds__(256) void k_cvtw6(
    W6 ws, __half* __restrict__ O, int K, int N, size_t ostride)
{
    __shared__ float tile[32][33];
    const float* W = ws.W[blockIdx.z];
    __half* Oz = O + blockIdx.z * ostride;
    int k0 = blockIdx.x * 32, n0 = blockIdx.y * 32;
    int tx = threadIdx.x & 31, ty = threadIdx.x >> 5;
    #pragma unroll
    for (int j = 0; j < 32; j += 8)
        tile[ty + j][tx] = W[(size_t)(k0 + ty + j) * N + n0 + tx];
    __syncthreads();
    #pragma unroll
    for (int j = 0; j < 32; j += 8) {
        int n = n0 + ty + j, k = k0 + tx;
        Oz[(size_t)n * K + k] = __float2half(tile[tx][ty + j]);
    }
}

// ==================== fp16 mma.sync GEMM ====================
struct TcB {
    const __half* W[5];
    const float* b[5];
    float* C[5];
};

#define STG_BYTES 32768
#define MM_STG 3
#define MM_SMEM (MM_STG*STG_BYTES)

template <int ACT>
__global__ __launch_bounds__(256, 2) void k_wmma(
    const __half* __restrict__ A, TcB bt, int N, int K)
{
    extern __shared__ char smem[];
    const int z = blockIdx.z;
    const __half* Bw = bt.W[z];
    const float* bias = bt.b[z];
    float* C = bt.C[z];
    const int m0 = blockIdx.y * 128, n0 = blockIdx.x * 128;
    int tid = threadIdx.x, lane = tid & 31, wid = tid >> 5;
    int wm = wid & 3, wn = wid >> 2;
    uint32_t sb = s2u(smem);

    const int NIT = K >> 6;

    int lr = tid & 127;
    int half_ = tid >> 7;
    const char* gAr = (const char*)(A + (size_t)(m0 + lr) * K);
    const char* gBr = (const char*)(Bw + (size_t)(n0 + lr) * K);
    uint32_t stoff[4];
    uint32_t gcol[4];
    #pragma unroll
    for (int j = 0; j < 4; j++) {
        int c16 = half_ * 4 + j;
        stoff[j] = (uint32_t)(lr * 128 + ((c16 ^ (lr & 7)) << 4));
        gcol[j] = (uint32_t)(c16 << 4);
    }

    float acc[2][8][4];
    #pragma unroll
    for (int i = 0; i < 2; i++)
        #pragma unroll
        for (int j = 0; j < 8; j++)
            #pragma unroll
            for (int c = 0; c < 4; c++) acc[i][j][c] = 0.0f;

    auto issue = [&](int t) {
        int b = t % MM_STG;
        uint32_t base = sb + b * STG_BYTES;
        size_t off = (size_t)t * 128;
        #pragma unroll
        for (int j = 0; j < 4; j++) cp16(base + stoff[j], gAr + off + gcol[j]);
        #pragma unroll
        for (int j = 0; j < 4; j++) cp16(base + 16384 + stoff[j], gBr + off + gcol[j]);
        asm volatile("cp.async.commit_group;" ::: "memory");
    };
    issue(0); issue(1);

    int lrow = lane & 15, lk8 = lane >> 4, rxor = lrow & 7;
    uint32_t aRow = (uint32_t)((wm * 32 + lrow) * 128);
    uint32_t bRow = (uint32_t)((wn * 64 + lrow) * 128);
    uint32_t swz[4];
    #pragma unroll
    for (int kk = 0; kk < 4; kk++)
        swz[kk] = (uint32_t)((((kk * 2) + lk8) ^ rxor) << 4);

    for (int t = 0; t < NIT; t++) {
        if (t == NIT - 1) asm volatile("cp.async.wait_group 0;" ::: "memory");
        else              asm volatile("cp.async.wait_group 1;" ::: "memory");
        __syncthreads();
        if (t + 2 < NIT) issue(t + 2);

        int b = t % MM_STG;
        uint32_t aBase = sb + b * STG_BYTES + aRow;
        uint32_t bBase = sb + b * STG_BYTES + 16384 + bRow;
        #pragma unroll
        for (int kk = 0; kk < 4; kk++) {
            uint32_t ar[2][4], br[4][4];
            #pragma unroll
            for (int mf = 0; mf < 2; mf++)
                ldsm4(ar[mf], aBase + mf * (16 * 128) + swz[kk]);
            #pragma unroll
            for (int nf = 0; nf < 4; nf++)
                ldsm4(br[nf], bBase + nf * (16 * 128) + swz[kk]);
            #pragma unroll
            for (int mf = 0; mf < 2; mf++)
                #pragma unroll
                for (int ns = 0; ns < 8; ns++)
                    mma_f16(acc[mf][ns], ar[mf],
                            br[ns >> 1][ns & 1], br[ns >> 1][(ns & 1) + 2]);
        }
    }

    int erow = lane >> 2, ecol = (lane & 3) * 2;
    #pragma unroll
    for (int mf = 0; mf < 2; mf++) {
        int r0 = m0 + wm * 32 + mf * 16 + erow;
        #pragma unroll
        for (int ns = 0; ns < 8; ns++) {
            int cc = n0 + wn * 64 + ns * 8 + ecol;
            float b0 = bias[cc], b1 = bias[cc + 1];
            float v0 = acc[mf][ns][0] + b0;
            float v1 = acc[mf][ns][1] + b1;
            float v2 = acc[mf][ns][2] + b0;
            float v3 = acc[mf][ns][3] + b1;
            if (ACT == 0) {
                *reinterpret_cast<float2*>(&C[(size_t)r0 * N + cc])       = make_float2(v0, v1);
                *reinterpret_cast<float2*>(&C[(size_t)(r0 + 8) * N + cc]) = make_float2(v2, v3);
            } else {
                if (ACT == 1) {
                    v0 = 0.5f * v0 * (1.0f + erff(v0 * 0.70710678118654752440f));
                    v1 = 0.5f * v1 * (1.0f + erff(v1 * 0.70710678118654752440f));
                    v2 = 0.5f * v2 * (1.0f + erff(v2 * 0.70710678118654752440f));
                    v3 = 0.5f * v3 * (1.0f + erff(v3 * 0.70710678118654752440f));
                }
                __half* C16 = (__half*)C;
                *reinterpret_cast<__half2*>(&C16[(size_t)r0 * N + cc]) =
                    __halves2half2(__float2half(v0), __float2half(v1));
                *reinterpret_cast<__half2*>(&C16[(size_t)(r0 + 8) * N + cc]) =
                    __halves2half2(__float2half(v2), __float2half(v3));
            }
        }
    }
}

// ==================== non-GEMM kernels ====================
__global__ __launch_bounds__(256) void k_embed(
    const int* __restrict__ ids, const float* __restrict__ wemb,
    const float* __restrict__ pemb, const float* __restrict__ lns,
    const float* __restrict__ lnb, float* __restrict__ xout,
    __half* __restrict__ x16)
{
    __shared__ float red[32];
    int row = blockIdx.x;
    int tid = threadIdx.x;
    int s = row & (SS - 1);
    int id = ids[row];
    const float* we = wemb + (size_t)id * HID;
    const float* pe = pemb + (size_t)s * HID;
    float v0 = we[tid]       + pe[tid];
    float v1 = we[tid + 256] + pe[tid + 256];
    float v2 = we[tid + 512] + pe[tid + 512];
    float mean = blk_sum256(v0 + v1 + v2, red) * (1.0f / HID);
    v0 -= mean; v1 -= mean; v2 -= mean;
    float var = blk_sum256(v0*v0 + v1*v1 + v2*v2, red) * (1.0f / HID);
    float r = rsqrtf(var + 1e-5f);
    size_t base = (size_t)row * HID;
    float o0 = v0 * r * lns[tid]       + lnb[tid];
    float o1 = v1 * r * lns[tid + 256] + lnb[tid + 256];
    float o2 = v2 * r * lns[tid + 512] + lnb[tid + 512];
    xout[base + tid]       = o0;
    xout[base + tid + 256] = o1;
    xout[base + tid + 512] = o2;
    x16[base + tid]        = __float2half(o0);
    x16[base + tid + 256]  = __float2half(o1);
    x16[base + tid + 512]  = __float2half(o2);
}

__global__ __launch_bounds__(256) void k_addln(
    const float* __restrict__ add, const float* __restrict__ lns,
    const float* __restrict__ lnb, float* __restrict__ x,
    __half* __restrict__ x16)
{
    __shared__ float red[32];
    int row = blockIdx.x;
    int tid = threadIdx.x;
    size_t base = (size_t)row * HID;
    float v0 = x[base + tid]       + add[base + tid];
    float v1 = x[base + tid + 256] + add[base + tid + 256];
    float v2 = x[base + tid + 512] + add[base + tid + 512];
    float mean = blk_sum256(v0 + v1 + v2, red) * (1.0f / HID);
    v0 -= mean; v1 -= mean; v2 -= mean;
    float var = blk_sum256(v0*v0 + v1*v1 + v2*v2, red) * (1.0f / HID);
    float r = rsqrtf(var + 1e-5f);
    float o0 = v0 * r * lns[tid]       + lnb[tid];
    float o1 = v1 * r * lns[tid + 256] + lnb[tid + 256];
    float o2 = v2 * r * lns[tid + 512] + lnb[tid + 512];
    x[base + tid]       = o0;
    x[base + tid + 256] = o1;
    x[base + tid + 512] = o2;
    x16[base + tid]       = __float2half(o0);
    x16[base + tid + 256] = __float2half(o1);
    x16[base + tid + 512] = __float2half(o2);
}

__global__ __launch_bounds__(256) void k_qg0(
    const float* __restrict__ x, const float* __restrict__ Wg,
    const float* __restrict__ bg, float* __restrict__ outq)
{
    int b = blockIdx.y;
    int n = blockIdx.x * 256 + threadIdx.x;
    __shared__ float xs[HID];
    for (int i = threadIdx.x; i < HID; i += 256) xs[i] = x[(size_t)b * SS * HID + i];
    __syncthreads();
    float acc = bg[n];
    for (int kk = 0; kk < HID; kk++) acc = fmaf(xs[kk], Wg[(size_t)kk * HID + n], acc);
    outq[b * HID + n] = acc;
}

// ---- banded attention: 128-query blocks, 3 CTAs/SM, f32x2 packed FMA ----
#define KT 32
#define NTILE2 20
// smem: 3 stages x (K 8KB + V 8KB) | scs 16KB | kg0 | vg0 | kval(640)
#define BAND_SMEM (49152 + 16384 + 256 + 256 + 640)

__global__ __launch_bounds__(128, 3) void k_band(
    const float* __restrict__ q, const float* __restrict__ k,
    const float* __restrict__ v, const float* __restrict__ kg,
    const float* __restrict__ vg, const int* __restrict__ am,
    __half* __restrict__ out)
{
    extern __shared__ char sm[];
    float* scs = (float*)(sm + 49152);               // [KT][128]
    float* kg0 = (float*)(sm + 65536);               // [DH]
    float* vg0 = (float*)(sm + 65792);               // [DH]
    unsigned char* kval = (unsigned char*)(sm + 66048); // [640]
    uint32_t sb = s2u(sm);

    int c = blockIdx.x >> 1, s_ = blockIdx.x & 1;
    int h = blockIdx.y, b = blockIdx.z;
    int tid = threadIdx.x;                // 0..127; one query per thread
    int qpos = c * WW + s_ * 128 + tid;
    int cstart = (c - 1) * WW + s_ * 128; // block-local key origin

    if (tid < DH) {
        kg0[tid] = kg[(size_t)(b * SS) * HID + h * DH + tid];
        vg0[tid] = vg[(size_t)(b * SS) * HID + h * DH + tid];
    }
    for (int j = tid; j < NTILE2 * KT; j += 128) {
        int kp = cstart + j;
        kval[j] = (kp > 0 && kp < SS && am[b * SS + kp] > 0) ? 1 : 0;
    }

    // loader: 4 chunks per matrix per thread (32 keys x 16 chunks = 512 / 128)
    uint32_t stc[4];
    int jjc[4], ddc[4];
    #pragma unroll
    for (int i = 0; i < 4; i++) {
        int ci = tid + i * 128;
        jjc[i] = ci >> 4;
        ddc[i] = ci & 15;
        stc[i] = (uint32_t)(jjc[i] * 256 + ddc[i] * 16);
    }

    auto issue = [&](int t) {
        uint32_t base = sb + (t % 3) * 16384;
        int kt0 = t * KT;
        #pragma unroll
        for (int i = 0; i < 4; i++) {
            int kp = min(max(cstart + kt0 + jjc[i], 0), SS - 1);
            size_t g = (size_t)(b * SS + kp) * HID + h * DH + ddc[i] * 4;
            cp16(base + stc[i], k + g);
            cp16(base + 8192 + stc[i], v + g);
        }
        asm volatile("cp.async.commit_group;" ::: "memory");
    };
    issue(0); issue(1);

    // q packed into 32 u64
    unsigned long long qv2[32];
    {
        const float4* qp4 = reinterpret_cast<const float4*>(
            q + (size_t)(b * SS + qpos) * HID + h * DH);
        #pragma unroll
        for (int i = 0; i < 16; i++) {
            float4 qf = qp4[i];
            qv2[2 * i]     = pk2(qf.x, qf.y);
            qv2[2 * i + 1] = pk2(qf.z, qf.w);
        }
    }
    __syncthreads();   // kg0/vg0/kval ready

    // init online softmax with the global (CLS key) column
    float m;
    {
        unsigned long long a0 = 0ULL, a1 = 0ULL, a2 = 0ULL, a3 = 0ULL;
        const ulonglong2* g8 = reinterpret_cast<const ulonglong2*>(kg0);
        #pragma unroll
        for (int i = 0; i < 16; i += 2) {
            ulonglong2 ka = g8[i], kb = g8[i + 1];
            fma2(a0, qv2[2*i],     ka.x);
            fma2(a1, qv2[2*i + 1], ka.y);
            fma2(a2, qv2[2*i + 2], kb.x);
            fma2(a3, qv2[2*i + 3], kb.y);
        }
        float2 f0 = upk2(a0), f1 = upk2(a1), f2 = upk2(a2), f3 = upk2(a3);
        m = ((f0.x + f0.y) + (f1.x + f1.y) + (f2.x + f2.y) + (f3.x + f3.y)) * 0.125f;
    }
    float l = 1.0f;
    unsigned long long accv2[32];
    #pragma unroll
    for (int i = 0; i < 32; i++) accv2[i] = pk2(vg0[2 * i], vg0[2 * i + 1]);

    for (int t = 0; t < NTILE2; t++) {
        if (t == NTILE2 - 1) asm volatile("cp.async.wait_group 0;" ::: "memory");
        else                 asm volatile("cp.async.wait_group 1;" ::: "memory");
        __syncthreads();
        if (t + 2 < NTILE2) issue(t + 2);

        int kt0 = t * KT;
        const char* kb = sm + (t % 3) * 16384;
        const char* vb = kb + 8192;

        // band: block-local key jb valid for this query iff tid <= jb <= tid+512
        int jlo = max(tid - kt0, 0);
        int jhi = min(tid + 2 * WW - kt0, KT - 1);

        // pass 1: scores via packed fma, tile max
        float tmax = -3.0e38f;
        for (int jj = jlo; jj <= jhi; jj++) {
            int j = kt0 + jj;
            if (!kval[j]) continue;
            const ulonglong2* kp8 = (const ulonglong2*)(kb + jj * 256);
            unsigned long long a0 = 0ULL, a1 = 0ULL, a2 = 0ULL, a3 = 0ULL;
            #pragma unroll
            for (int i = 0; i < 16; i += 2) {
                ulonglong2 ka = kp8[i], kbv = kp8[i + 1];
                fma2(a0, qv2[2*i],     ka.x);
                fma2(a1, qv2[2*i + 1], ka.y);
                fma2(a2, qv2[2*i + 2], kbv.x);
                fma2(a3, qv2[2*i + 3], kbv.y);
            }
            float2 f0 = upk2(a0), f1 = upk2(a1), f2 = upk2(a2), f3 = upk2(a3);
            float sc = ((f0.x + f0.y) + (f1.x + f1.y) + (f2.x + f2.y) + (f3.x + f3.y)) * 0.125f;
            scs[jj * 128 + tid] = sc;
            tmax = fmaxf(tmax, sc);
        }
        if (tmax > -1.0e37f) {
            if (tmax > m) {
                float fac = __expf(m - tmax);
                l *= fac;
                unsigned long long f2p = pk2(fac, fac);
                #pragma unroll
                for (int i = 0; i < 32; i++) accv2[i] = mul2(accv2[i], f2p);
                m = tmax;
            }
            // pass 2: single exp per key + packed PV accumulate
            for (int jj = jlo; jj <= jhi; jj++) {
                int j = kt0 + jj;
                if (!kval[j]) continue;
                float w = __expf(scs[jj * 128 + tid] - m);
                l += w;
                unsigned long long w2 = pk2(w, w);
                const ulonglong2* vp8 = (const ulonglong2*)(vb + jj * 256);
                #pragma unroll
                for (int i = 0; i < 16; i++) {
                    ulonglong2 vv = vp8[i];
                    fma2(accv2[2 * i],     w2, vv.x);
                    fma2(accv2[2 * i + 1], w2, vv.y);
                }
            }
        }
    }
    float inv = 1.0f / l;
    __half* op = out + (size_t)(b * SS + qpos) * HID + h * DH;
    #pragma unroll
    for (int i = 0; i < 16; i++) {
        float2 fa = upk2(accv2[2 * i]);
        float2 fb = upk2(accv2[2 * i + 1]);
        *reinterpret_cast<__half2*>(op + i * 4) =
            __floats2half2_rn(fa.x * inv, fa.y * inv);
        *reinterpret_cast<__half2*>(op + i * 4 + 2) =
            __floats2half2_rn(fb.x * inv, fb.y * inv);
    }
}

// ---- global CLS row: split over 16 seq chunks (f32x2), then merge ----
__global__ __launch_bounds__(256) void k_glob1(
    const float* __restrict__ qg0, const float* __restrict__ kg,
    const float* __restrict__ vg, const int* __restrict__ am,
    float* __restrict__ gm, float* __restrict__ gl, float* __restrict__ go)
{
    int c = blockIdx.x;             // 0..15
    int bh = blockIdx.y;            // 0..23
    int b = bh / HEADS, h = bh % HEADS;
    int tid = threadIdx.x;
    __shared__ __align__(16) float q0[DH];
    __shared__ float sc[256];
    __shared__ float red[32];
    __shared__ __align__(16) unsigned long long part2[8][32];

    if (tid < DH) q0[tid] = qg0[b * HID + h * DH + tid];
    __syncthreads();

    int j = c * 256 + tid;
    float sv = -1e9f;
    if (am[b * SS + j] > 0) {
        const ulonglong2* kr8 = reinterpret_cast<const ulonglong2*>(
            kg + (size_t)(b * SS + j) * HID + h * DH);
        const ulonglong2* q8 = reinterpret_cast<const ulonglong2*>(q0);
        unsigned long long a0 = 0ULL, a1 = 0ULL, a2 = 0ULL, a3 = 0ULL;
        #pragma unroll
        for (int i = 0; i < 16; i += 2) {
            ulonglong2 ka = kr8[i], kbv = kr8[i + 1];
            ulonglong2 qa = q8[i],  qb  = q8[i + 1];
            fma2(a0, qa.x, ka.x);
            fma2(a1, qa.y, ka.y);
            fma2(a2, qb.x, kbv.x);
            fma2(a3, qb.y, kbv.y);
        }
        float2 f0 = upk2(a0), f1 = upk2(a1), f2 = upk2(a2), f3 = upk2(a3);
        sv = ((f0.x + f0.y) + (f1.x + f1.y) + (f2.x + f2.y) + (f3.x + f3.y)) * 0.125f;
    }
    float mc = blk_max256(sv, red);
    float w = (sv > -1.0e8f) ? __expf(sv - mc) : 0.0f;
    sc[tid] = w;
    float lc = blk_sum256(w, red);
    __syncthreads();

    int d2 = tid & 31, g = tid >> 5;
    unsigned long long acc2 = 0ULL;
    #pragma unroll 4
    for (int jj = g * 32; jj < g * 32 + 32; jj++) {
        unsigned long long w2 = pk2(sc[jj], sc[jj]);
        const unsigned long long* vr = reinterpret_cast<const unsigned long long*>(
            vg + (size_t)(b * SS + c * 256 + jj) * HID + h * DH);
        fma2(acc2, w2, vr[d2]);
    }
    part2[g][d2] = acc2;
    __syncthreads();
    if (tid < 32) {
        float2 t = upk2(part2[0][tid]);
        #pragma unroll
        for (int gg = 1; gg < 8; gg++) {
            float2 u = upk2(part2[gg][tid]);
            t.x += u.x; t.y += u.y;
        }
        go[((size_t)bh * 16 + c) * DH + 2 * tid]     = t.x;
        go[((size_t)bh * 16 + c) * DH + 2 * tid + 1] = t.y;
    }
    if (tid == 0) { gm[bh * 16 + c] = mc; gl[bh * 16 + c] = lc; }
}

__global__ __launch_bounds__(64) void k_glob2(
    const float* __restrict__ gm, const float* __restrict__ gl,
    const float* __restrict__ go, __half* __restrict__ out)
{
    int bh = blockIdx.x;
    int b = bh / HEADS, h = bh % HEADS;
    int d = threadIdx.x;
    float mstar = -3.0e38f;
    #pragma unroll
    for (int c = 0; c < 16; c++) mstar = fmaxf(mstar, gm[bh * 16 + c]);
    float lsum = 0.0f, osum = 0.0f;
    #pragma unroll
    for (int c = 0; c < 16; c++) {
        float e = __expf(gm[bh * 16 + c] - mstar);
        lsum += gl[bh * 16 + c] * e;
        osum += go[((size_t)bh * 16 + c) * DH + d] * e;
    }
    out[(size_t)(b * SS) * HID + h * DH + d] = __float2half(osum / lsum);
}

// ---- classifier head: 64-label tiles x 4-way K split ----
__global__ __launch_bounds__(256) void k_head(
    const float* __restrict__ x, const float* __restrict__ hw,
    const float* __restrict__ hb, float* __restrict__ out)
{
    int b = blockIdx.y;
    int n0 = blockIdx.x * 64;
    int lbl = threadIdx.x & 63;
    int kc = threadIdx.x >> 6;          // 0..3
    __shared__ float xs[HID];
    __shared__ float partial[4][64];
    for (int i = threadIdx.x; i < HID; i += 256) xs[i] = x[(size_t)b * SS * HID + i];
    __syncthreads();
    int n = n0 + lbl;
    float acc = 0.0f;
    if (n < NLAB) {
        #pragma unroll 4
        for (int kk = kc * 192; kk < kc * 192 + 192; kk++)
            acc = fmaf(xs[kk], hw[(size_t)kk * NLAB + n], acc);
    }
    partial[kc][lbl] = acc;
    __syncthreads();
    if (threadIdx.x < 64) {
        int nn = n0 + threadIdx.x;
        if (nn < NLAB)
            out[(size_t)b * NLAB + nn] = partial[0][threadIdx.x] + partial[1][threadIdx.x]
                + partial[2][threadIdx.x] + partial[3][threadIdx.x] + hb[nn];
    }
}

// ==================== orchestration ====================
extern "C" void kernel_launch(void* const* d_in, const int* in_sizes, int n_in,
                              void* d_out, int out_size)
{
    const int*   ids  = (const int*)d_in[0];
    const int*   am   = (const int*)d_in[1];
    const float* wemb = (const float*)d_in[2];
    const float* pemb = (const float*)d_in[3];
    const float* elns = (const float*)d_in[4];
    const float* elnb = (const float*)d_in[5];
    const float* Wq   = (const float*)d_in[6];
    const float* bq   = (const float*)d_in[7];
    const float* Wk   = (const float*)d_in[8];
    const float* bk   = (const float*)d_in[9];
    const float* Wv   = (const float*)d_in[10];
    const float* bv   = (const float*)d_in[11];
    const float* Wqg  = (const float*)d_in[12];
    const float* bqg  = (const float*)d_in[13];
    const float* Wkg  = (const float*)d_in[14];
    const float* bkg  = (const float*)d_in[15];
    const float* Wvg  = (const float*)d_in[16];
    const float* bvg  = (const float*)d_in[17];
    const float* Wo   = (const float*)d_in[18];
    const float* bo   = (const float*)d_in[19];
    const float* ln1s = (const float*)d_in[20];
    const float* ln1b = (const float*)d_in[21];
    const float* W1   = (const float*)d_in[22];
    const float* b1   = (const float*)d_in[23];
    const float* W2   = (const float*)d_in[24];
    const float* b2   = (const float*)d_in[25];
    const float* ln2s = (const float*)d_in[26];
    const float* ln2b = (const float*)d_in[27];
    const float* hW   = (const float*)d_in[28];
    const float* hb   = (const float*)d_in[29];
    float* out = (float*)d_out;

    float *px, *pq, *pk, *pv, *pkg, *pvg, *ptmp, *pqg0, *pgm, *pgl, *pgo;
    __half *pwt, *pw1t, *pw2t, *pab, *pab2;
    cudaGetSymbolAddress((void**)&px,   g_x);
    cudaGetSymbolAddress((void**)&pq,   g_q);
    cudaGetSymbolAddress((void**)&pk,   g_k);
    cudaGetSymbolAddress((void**)&pv,   g_v);
    cudaGetSymbolAddress((void**)&pkg,  g_kg);
    cudaGetSymbolAddress((void**)&pvg,  g_vg);
    cudaGetSymbolAddress((void**)&ptmp, g_tmp);
    cudaGetSymbolAddress((void**)&pqg0, g_qg0);
    cudaGetSymbolAddress((void**)&pgm,  g_gm);
    cudaGetSymbolAddress((void**)&pgl,  g_gl);
    cudaGetSymbolAddress((void**)&pgo,  g_go);
    cudaGetSymbolAddress((void**)&pwt,  g_wt);
    cudaGetSymbolAddress((void**)&pw1t, g_w1t);
    cudaGetSymbolAddress((void**)&pw2t, g_w2t);
    cudaGetSymbolAddress((void**)&pab,  g_ab);
    cudaGetSymbolAddress((void**)&pab2, g_ab2);

    cudaFuncSetAttribute(k_wmma<0>, cudaFuncAttributeMaxDynamicSharedMemorySize, MM_SMEM);
    cudaFuncSetAttribute(k_wmma<1>, cudaFuncAttributeMaxDynamicSharedMemorySize, MM_SMEM);
    cudaFuncSetAttribute(k_band, cudaFuncAttributeMaxDynamicSharedMemorySize, BAND_SMEM);

    const size_t WSTRIDE = (size_t)HID * HID;

    // ---- weight conversions (batched) ----
    for (int l = 0; l < 2; l++) {
        size_t ow  = (size_t)l * HID * HID;
        size_t ow1 = (size_t)l * HID * FFNDIM;
        W6 ws;
        ws.W[0] = Wq + ow; ws.W[1] = Wk + ow; ws.W[2] = Wv + ow;
        ws.W[3] = Wkg + ow; ws.W[4] = Wvg + ow; ws.W[5] = Wo + ow;
        k_cvtw6<<<dim3(HID / 32, HID / 32, 6), 256>>>(
            ws, pwt + (size_t)(l * 6) * WSTRIDE, HID, HID, WSTRIDE);
        W6 w1; w1.W[0] = W1 + ow1;
        k_cvtw6<<<dim3(HID / 32, FFNDIM / 32, 1), 256>>>(
            w1, pw1t + (size_t)l * FFNDIM * HID, HID, FFNDIM, 0);
        W6 w2; w2.W[0] = W2 + ow1;
        k_cvtw6<<<dim3(FFNDIM / 32, HID / 32, 1), 256>>>(
            w2, pw2t + (size_t)l * HID * FFNDIM, FFNDIM, HID, 0);
    }

    k_embed<<<NTOK, 256>>>(ids, wemb, pemb, elns, elnb, px, pab2);

    for (int l = 0; l < 2; l++) {
        size_t ow  = (size_t)l * HID * HID;
        size_t ob  = (size_t)l * HID;
        size_t ob1 = (size_t)l * FFNDIM;
        const __half* wl = pwt + (size_t)(l * 6) * WSTRIDE;

        // 5 projections batched (input pab2 = fp16 of x), fp32 outputs
        {
            TcB b5;
            b5.W[0] = wl + 0 * WSTRIDE; b5.b[0] = bq  + ob; b5.C[0] = pq;
            b5.W[1] = wl + 1 * WSTRIDE; b5.b[1] = bk  + ob; b5.C[1] = pk;
            b5.W[2] = wl + 2 * WSTRIDE; b5.b[2] = bv  + ob; b5.C[2] = pv;
            b5.W[3] = wl + 3 * WSTRIDE; b5.b[3] = bkg + ob; b5.C[3] = pkg;
            b5.W[4] = wl + 4 * WSTRIDE; b5.b[4] = bvg + ob; b5.C[4] = pvg;
            k_wmma<0><<<dim3(HID / 128, NTOK / 128, 5), 256, MM_SMEM>>>(pab2, b5, HID, HID);
        }
        k_qg0<<<dim3(3, BB), 256>>>(px, Wqg + ow, bqg + ob, pqg0);

        // attention writes fp16 directly into pab2
        k_band<<<dim3(NC * 2, HEADS, BB), 128, BAND_SMEM>>>(pq, pk, pv, pkg, pvg, am, pab2);
        k_glob1<<<dim3(16, BB * HEADS), 256>>>(pqg0, pkg, pvg, am, pgm, pgl, pgo);
        k_glob2<<<BB * HEADS, 64>>>(pgm, pgl, pgo, pab2);

        // attn @ Wo
        {
            TcB bo5; bo5.W[0] = wl + 5 * WSTRIDE; bo5.b[0] = bo + ob; bo5.C[0] = ptmp;
            bo5.W[1] = bo5.W[0]; bo5.b[1] = bo5.b[0]; bo5.C[1] = bo5.C[0];
            bo5.W[2] = bo5.W[0]; bo5.b[2] = bo5.b[0]; bo5.C[2] = bo5.C[0];
            bo5.W[3] = bo5.W[0]; bo5.b[3] = bo5.b[0]; bo5.C[3] = bo5.C[0];
            bo5.W[4] = bo5.W[0]; bo5.b[4] = bo5.b[0]; bo5.C[4] = bo5.C[0];
            k_wmma<0><<<dim3(HID / 128, NTOK / 128, 1), 256, MM_SMEM>>>(pab2, bo5, HID, HID);
        }
        k_addln<<<NTOK, 256>>>(ptmp, ln1s + ob, ln1b + ob, px, pab2);

        // FFN: W1 writes GELU'd fp16 directly into pab
        {
            TcB bw1; bw1.W[0] = pw1t + (size_t)l * FFNDIM * HID; bw1.b[0] = b1 + ob1;
            bw1.C[0] = (float*)pab;
            bw1.W[1] = bw1.W[0]; bw1.b[1] = bw1.b[0]; bw1.C[1] = bw1.C[0];
            bw1.W[2] = bw1.W[0]; bw1.b[2] = bw1.b[0]; bw1.C[2] = bw1.C[0];
            bw1.W[3] = bw1.W[0]; bw1.b[3] = bw1.b[0]; bw1.C[3] = bw1.C[0];
            bw1.W[4] = bw1.W[0]; bw1.b[4] = bw1.b[0]; bw1.C[4] = bw1.C[0];
            k_wmma<1><<<dim3(FFNDIM / 128, NTOK / 128, 1), 256, MM_SMEM>>>(pab2, bw1, FFNDIM, HID);
        }
        {
            TcB bw2; bw2.W[0] = pw2t + (size_t)l * HID * FFNDIM; bw2.b[0] = b2 + ob; bw2.C[0] = ptmp;
            bw2.W[1] = bw2.W[0]; bw2.b[1] = bw2.b[0]; bw2.C[1] = bw2.C[0];
            bw2.W[2] = bw2.W[0]; bw2.b[2] = bw2.b[0]; bw2.C[2] = bw2.C[0];
            bw2.W[3] = bw2.W[0]; bw2.b[3] = bw2.b[0]; bw2.C[3] = bw2.C[0];
            bw2.W[4] = bw2.W[0]; bw2.b[4] = bw2.b[0]; bw2.C[4] = bw2.C[0];
            k_wmma<0><<<dim3(HID / 128, NTOK / 128, 1), 256, MM_SMEM>>>(pab, bw2, HID, FFNDIM);
        }
        k_addln<<<NTOK, 256>>>(ptmp, ln2s + ob, ln2b + ob, px, pab2);
    }

    k_head<<<dim3((NLAB + 63) / 64, BB), 256>>>(px, hW, hb, out);
}